// round 7
// baseline (speedup 1.0000x reference)
#include <cuda_runtime.h>
#include <cstdint>

#define NN   100000
#define EMAX 1600000
#define F    16

typedef unsigned long long ull;

// ---------------- scratch (static __device__, no allocs) ----------------
__device__ int g_deg[NN];
__device__ int g_cur[NN];
__device__ int g_off[NN + 1];
__device__ int g_bsum[128];
__device__ __align__(16) int2  g_sd[EMAX];                 // sorted (src,dst)
__device__ __align__(16) float g_eas[(size_t)EMAX * 8];    // sorted edge_attr
__device__ __align__(16) float g_m[(size_t)EMAX * F];      // messages (reused by both layers)
__device__ __align__(16) float g_P1[NN * F];               // conv1 src-partial
__device__ __align__(16) float g_P2[NN * F];               // conv2 src-partial
__device__ __align__(16) float g_h1[NN * F];
__device__ __align__(16) float g_h2[NN * F];
__device__ int g_idx64;

// ---------------- weights in constant memory ----------------
__constant__ __align__(16) float c1w1[16 * F];
__constant__ __align__(16) float c1b1[F];
__constant__ __align__(16) float c1w2[F * F];
__constant__ __align__(16) float c1b2[F];
__constant__ __align__(16) float c2w1[40 * F];
__constant__ __align__(16) float c2b1[F];
__constant__ __align__(16) float c2w2[F * F];
__constant__ __align__(16) float c2b2[F];
__constant__ __align__(16) float clw1[F * F];
__constant__ __align__(16) float clb1[F];
__constant__ __align__(16) float clw2[F];
__constant__ float clb2[1];

// ---------------- f32x2 packed helpers ----------------
__device__ __forceinline__ ull pk2(float a, float b) {
    ull r; asm("mov.b64 %0, {%1, %2};" : "=l"(r) : "f"(a), "f"(b)); return r;
}
__device__ __forceinline__ ull bcast2(float a) {
    ull r; asm("mov.b64 %0, {%1, %1};" : "=l"(r) : "f"(a)); return r;
}
__device__ __forceinline__ void upk2(ull v, float& a, float& b) {
    asm("mov.b64 {%0, %1}, %2;" : "=f"(a), "=f"(b) : "l"(v));
}
__device__ __forceinline__ ull fma2(ull a, ull b, ull c) {
    ull d; asm("fma.rn.f32x2 %0, %1, %2, %3;" : "=l"(d) : "l"(a), "l"(b), "l"(c)); return d;
}

// ---------------- preprocessing ----------------
__global__ void detect_kernel(const void* ei, int N) {
    const long long* p64 = (const long long*)ei;
    bool ok = true;
#pragma unroll
    for (int k = 0; k < 4; k++) {
        long long v = p64[k];
        if (v < 0 || v >= N) ok = false;
    }
    g_idx64 = ok ? 1 : 0;
}

__global__ void zero_deg_kernel(int n) {
    int i = blockIdx.x * blockDim.x + threadIdx.x;
    if (i < n) g_deg[i] = 0;
}

__global__ void hist_kernel(const void* __restrict__ ei, int E) {
    int e = blockIdx.x * blockDim.x + threadIdx.x;
    if (e >= E) return;
    int s = g_idx64 ? (int)((const long long*)ei)[e] : ((const int*)ei)[e];
    atomicAdd(&g_deg[s], 1);
}

__global__ void __launch_bounds__(1024) scan_blocks_kernel(int n) {
    __shared__ int wsum[32];
    int i = blockIdx.x * 1024 + threadIdx.x;
    int lane = threadIdx.x & 31;
    int wid  = threadIdx.x >> 5;
    int v = (i < n) ? g_deg[i] : 0;
    int s = v;
#pragma unroll
    for (int o = 1; o < 32; o <<= 1) {
        int t = __shfl_up_sync(~0u, s, o);
        if (lane >= o) s += t;
    }
    if (lane == 31) wsum[wid] = s;
    __syncthreads();
    if (wid == 0) {
        int ws = wsum[lane];
#pragma unroll
        for (int o = 1; o < 32; o <<= 1) {
            int t = __shfl_up_sync(~0u, ws, o);
            if (lane >= o) ws += t;
        }
        wsum[lane] = ws;
    }
    __syncthreads();
    int excl = s - v + (wid > 0 ? wsum[wid - 1] : 0);
    if (i < n) g_off[i] = excl;
    if (threadIdx.x == 1023) g_bsum[blockIdx.x] = wsum[31];
}

__global__ void __launch_bounds__(128) scan_tops_kernel(int nb) {
    __shared__ int wsum[4];
    int lane = threadIdx.x & 31;
    int wid  = threadIdx.x >> 5;
    int v = (threadIdx.x < nb) ? g_bsum[threadIdx.x] : 0;
    int s = v;
#pragma unroll
    for (int o = 1; o < 32; o <<= 1) {
        int t = __shfl_up_sync(~0u, s, o);
        if (lane >= o) s += t;
    }
    if (lane == 31) wsum[wid] = s;
    __syncthreads();
    int base = 0;
#pragma unroll
    for (int k = 0; k < 4; k++) if (k < wid) base += wsum[k];
    if (threadIdx.x < nb) g_bsum[threadIdx.x] = base + s - v;
}

__global__ void __launch_bounds__(1024) add_offsets_kernel(int n, int E) {
    int i = blockIdx.x * 1024 + threadIdx.x;
    if (i < n) {
        int o = g_off[i] + g_bsum[blockIdx.x];
        g_off[i] = o;
        g_cur[i] = o;
    }
    if (i == 0) g_off[n] = E;
}

__global__ void scatter_kernel(const void* __restrict__ ei,
                               const float* __restrict__ ea, int E) {
    int e = blockIdx.x * blockDim.x + threadIdx.x;
    if (e >= E) return;
    int s, d;
    if (g_idx64) {
        const long long* p = (const long long*)ei;
        s = (int)p[e]; d = (int)p[(size_t)E + e];
    } else {
        const int* p = (const int*)ei;
        s = p[e]; d = p[(size_t)E + e];
    }
    int pos = atomicAdd(&g_cur[s], 1);
    g_sd[pos] = make_int2(s, d);
    float4 a0 = *(const float4*)(ea + (size_t)e * 8);
    float4 a1 = *(const float4*)(ea + (size_t)e * 8 + 4);
    *(float4*)(g_eas + (size_t)pos * 8)     = a0;
    *(float4*)(g_eas + (size_t)pos * 8 + 4) = a1;
}

// ---------------- P1: conv1 src-partial per node ----------------
__global__ void __launch_bounds__(256) p1_kernel(const float* __restrict__ x, int N) {
    int n = blockIdx.x * blockDim.x + threadIdx.x;
    if (n >= N) return;
    const ull* w1p = reinterpret_cast<const ull*>(c1w1);
    float4 xv = *(const float4*)(x + (size_t)n * 4);
    float in[4] = {xv.x, xv.y, xv.z, xv.w};
    ull H[8];
#pragma unroll
    for (int k = 0; k < 8; k++) H[k] = pk2(c1b1[2*k], c1b1[2*k+1]);
#pragma unroll
    for (int i = 0; i < 4; i++) {
        ull vv = bcast2(in[i]);
#pragma unroll
        for (int k = 0; k < 8; k++) H[k] = fma2(vv, w1p[i*8 + k], H[k]);
    }
    ull* out = (ull*)(g_P1 + (size_t)n * F);
#pragma unroll
    for (int k = 0; k < 8; k++) out[k] = H[k];
}

// ---------------- conv edge phases: one lane = one sorted edge ----------------
__global__ void __launch_bounds__(256) conv1_edge_kernel(const float* __restrict__ x, int E) {
    int p = blockIdx.x * blockDim.x + threadIdx.x;
    if (p >= E) return;

    const ull* w1p = reinterpret_cast<const ull*>(c1w1);
    const ull* w2p = reinterpret_cast<const ull*>(c1w2);

    int2 sd = g_sd[p];
    // H = P1[s] (bias + src rows already folded)
    ull H[8];
    {
        const ull* Pp = (const ull*)(g_P1 + (size_t)sd.x * F);
#pragma unroll
        for (int k = 0; k < 8; k++) H[k] = Pp[k];
    }
    float4 xj = *(const float4*)(x + (size_t)sd.y * 4);
    float4 a0 = *(const float4*)(g_eas + (size_t)p * 8);
    float4 a1 = *(const float4*)(g_eas + (size_t)p * 8 + 4);
    float in[12] = {xj.x, xj.y, xj.z, xj.w,
                    a0.x, a0.y, a0.z, a0.w, a1.x, a1.y, a1.z, a1.w};
#pragma unroll
    for (int i = 0; i < 12; i++) {
        ull vv = bcast2(in[i]);
#pragma unroll
        for (int k = 0; k < 8; k++) H[k] = fma2(vv, w1p[(4+i)*8 + k], H[k]);
    }

    ull O[8];
#pragma unroll
    for (int k = 0; k < 8; k++) O[k] = pk2(c1b2[2*k], c1b2[2*k+1]);
#pragma unroll
    for (int k = 0; k < 8; k++) {
        float a, b; upk2(H[k], a, b);
        a = fmaxf(a, 0.f); b = fmaxf(b, 0.f);
        ull va = bcast2(a), vb = bcast2(b);
#pragma unroll
        for (int m = 0; m < 8; m++) O[m] = fma2(va, w2p[(2*k)*8 + m], O[m]);
#pragma unroll
        for (int m = 0; m < 8; m++) O[m] = fma2(vb, w2p[(2*k+1)*8 + m], O[m]);
    }
    ull* mp = (ull*)(g_m + (size_t)p * F);
#pragma unroll
    for (int k = 0; k < 4; k++)
        *(longlong2*)(mp + 2*k) = make_longlong2((long long)O[2*k], (long long)O[2*k+1]);
}

__global__ void __launch_bounds__(256) conv2_edge_kernel(int E) {
    int p = blockIdx.x * blockDim.x + threadIdx.x;
    if (p >= E) return;

    const ull* w1p = reinterpret_cast<const ull*>(c2w1);
    const ull* w2p = reinterpret_cast<const ull*>(c2w2);

    int2 sd = g_sd[p];
    ull H[8];
    {
        const ull* Pp = (const ull*)(g_P2 + (size_t)sd.x * F);
#pragma unroll
        for (int k = 0; k < 8; k++) H[k] = Pp[k];
    }
    float in[24];
    {
        const float4* pd = (const float4*)(g_h1 + (size_t)sd.y * F);
#pragma unroll
        for (int q = 0; q < 4; q++) {
            float4 v = pd[q];
            in[q*4+0] = v.x; in[q*4+1] = v.y; in[q*4+2] = v.z; in[q*4+3] = v.w;
        }
        float4 a0 = *(const float4*)(g_eas + (size_t)p * 8);
        float4 a1 = *(const float4*)(g_eas + (size_t)p * 8 + 4);
        in[16] = a0.x; in[17] = a0.y; in[18] = a0.z; in[19] = a0.w;
        in[20] = a1.x; in[21] = a1.y; in[22] = a1.z; in[23] = a1.w;
    }
#pragma unroll
    for (int i = 0; i < 24; i++) {
        ull vv = bcast2(in[i]);
#pragma unroll
        for (int k = 0; k < 8; k++) H[k] = fma2(vv, w1p[(16+i)*8 + k], H[k]);
    }

    ull O[8];
#pragma unroll
    for (int k = 0; k < 8; k++) O[k] = pk2(c2b2[2*k], c2b2[2*k+1]);
#pragma unroll
    for (int k = 0; k < 8; k++) {
        float a, b; upk2(H[k], a, b);
        a = fmaxf(a, 0.f); b = fmaxf(b, 0.f);
        ull va = bcast2(a), vb = bcast2(b);
#pragma unroll
        for (int m = 0; m < 8; m++) O[m] = fma2(va, w2p[(2*k)*8 + m], O[m]);
#pragma unroll
        for (int m = 0; m < 8; m++) O[m] = fma2(vb, w2p[(2*k+1)*8 + m], O[m]);
    }
    ull* mp = (ull*)(g_m + (size_t)p * F);
#pragma unroll
    for (int k = 0; k < 4; k++)
        *(longlong2*)(mp + 2*k) = make_longlong2((long long)O[2*k], (long long)O[2*k+1]);
}

// ---------------- segmented max reductions (16 lanes = 16 feats per node) ----------------
// reduce1 also emits P2[n] = c2b1 + sum_k h1[n][k] * c2w1[k][:]
__global__ void __launch_bounds__(256) reduce1_kernel(int N) {
    int gid = blockIdx.x * blockDim.x + threadIdx.x;
    int node = gid >> 4;
    int j = gid & 15;
    bool valid = (node < N);
    int nodec = valid ? node : (N - 1);

    int start = g_off[nodec];
    int end   = g_off[nodec + 1];

    float acc = 0.f;   // clamp-at-0 built in (matches maximum(agg,0))
    for (int p = start; p < end; p++)
        acc = fmaxf(acc, g_m[(size_t)p * F + j]);

    if (valid) g_h1[(size_t)node * F + j] = acc;

    // P2: lane j accumulates column j over all k rows; h1[k] fetched via shfl
    float p2 = c2b1[j];
#pragma unroll
    for (int k = 0; k < F; k++) {
        float hk = __shfl_sync(0xFFFFFFFFu, acc, k, 16);
        p2 = fmaf(hk, c2w1[k * F + j], p2);
    }
    if (valid) g_P2[(size_t)node * F + j] = p2;
}

__global__ void __launch_bounds__(256) reduce2_kernel(int N) {
    int gid = blockIdx.x * blockDim.x + threadIdx.x;
    int node = gid >> 4;
    int j = gid & 15;
    if (node >= N) return;

    int start = g_off[node];
    int end   = g_off[node + 1];

    float acc = 0.f;
    for (int p = start; p < end; p++)
        acc = fmaxf(acc, g_m[(size_t)p * F + j]);

    g_h2[(size_t)node * F + j] = acc;
}

// ---------------- final node MLP (packed) ----------------
__global__ void __launch_bounds__(256) node_mlp_kernel(float* __restrict__ out, int n) {
    int i = blockIdx.x * blockDim.x + threadIdx.x;
    if (i >= n) return;

    const ull* w1p = reinterpret_cast<const ull*>(clw1);

    ull H[8];
#pragma unroll
    for (int k = 0; k < 8; k++) H[k] = pk2(clb1[2*k], clb1[2*k+1]);

    const float4* ph = (const float4*)(g_h2 + (size_t)i * F);
#pragma unroll
    for (int q = 0; q < 4; q++) {
        float4 v = ph[q];
        float hv[4] = {v.x, v.y, v.z, v.w};
#pragma unroll
        for (int r = 0; r < 4; r++) {
            ull vv = bcast2(hv[r]);
            int kk = q * 4 + r;
#pragma unroll
            for (int k = 0; k < 8; k++) H[k] = fma2(vv, w1p[kk*8 + k], H[k]);
        }
    }

    float acc = clb2[0];
#pragma unroll
    for (int k = 0; k < 8; k++) {
        float a, b; upk2(H[k], a, b);
        acc += fmaxf(a, 0.f) * clw2[2*k] + fmaxf(b, 0.f) * clw2[2*k+1];
    }
    out[i] = acc;
}

// ---------------- launch ----------------
extern "C" void kernel_launch(void* const* d_in, const int* in_sizes, int n_in,
                              void* d_out, int out_size)
{
    const float* x  = (const float*)d_in[0];
    const void*  ei = d_in[1];
    const float* ea = (const float*)d_in[2];

    int N = in_sizes[0] / 4;   // x is [N,4]
    int E = in_sizes[2] / 8;   // edge_attr is [E,8]
    float* out = (float*)d_out;

    cudaMemcpyToSymbolAsync(c1w1, d_in[3],  16 * F * sizeof(float), 0, cudaMemcpyDeviceToDevice);
    cudaMemcpyToSymbolAsync(c1b1, d_in[4],  F * sizeof(float),      0, cudaMemcpyDeviceToDevice);
    cudaMemcpyToSymbolAsync(c1w2, d_in[5],  F * F * sizeof(float),  0, cudaMemcpyDeviceToDevice);
    cudaMemcpyToSymbolAsync(c1b2, d_in[6],  F * sizeof(float),      0, cudaMemcpyDeviceToDevice);
    cudaMemcpyToSymbolAsync(c2w1, d_in[7],  40 * F * sizeof(float), 0, cudaMemcpyDeviceToDevice);
    cudaMemcpyToSymbolAsync(c2b1, d_in[8],  F * sizeof(float),      0, cudaMemcpyDeviceToDevice);
    cudaMemcpyToSymbolAsync(c2w2, d_in[9],  F * F * sizeof(float),  0, cudaMemcpyDeviceToDevice);
    cudaMemcpyToSymbolAsync(c2b2, d_in[10], F * sizeof(float),      0, cudaMemcpyDeviceToDevice);
    cudaMemcpyToSymbolAsync(clw1, d_in[11], F * F * sizeof(float),  0, cudaMemcpyDeviceToDevice);
    cudaMemcpyToSymbolAsync(clb1, d_in[12], F * sizeof(float),      0, cudaMemcpyDeviceToDevice);
    cudaMemcpyToSymbolAsync(clw2, d_in[13], F * sizeof(float),      0, cudaMemcpyDeviceToDevice);
    cudaMemcpyToSymbolAsync(clb2, d_in[14], 1 * sizeof(float),      0, cudaMemcpyDeviceToDevice);

    detect_kernel<<<1, 1>>>(ei, N);
    zero_deg_kernel<<<(N + 255) / 256, 256>>>(N);

    int eblocks = (E + 255) / 256;
    hist_kernel<<<eblocks, 256>>>(ei, E);

    int sblocks = (N + 1023) / 1024;
    scan_blocks_kernel<<<sblocks, 1024>>>(N);
    scan_tops_kernel<<<1, 128>>>(sblocks);
    add_offsets_kernel<<<sblocks, 1024>>>(N, E);

    scatter_kernel<<<eblocks, 256>>>(ei, ea, E);
    p1_kernel<<<(N + 255) / 256, 256>>>(x, N);

    conv1_edge_kernel<<<eblocks, 256>>>(x, E);

    int rblocks = ((N * 16) + 255) / 256;
    reduce1_kernel<<<rblocks, 256>>>(N);

    conv2_edge_kernel<<<eblocks, 256>>>(E);
    reduce2_kernel<<<rblocks, 256>>>(N);

    node_mlp_kernel<<<(N + 255) / 256, 256>>>(out, N);
}

// round 8
// speedup vs baseline: 1.8009x; 1.8009x over previous
#include <cuda_runtime.h>
#include <cstdint>

#define NN   100000
#define EMAX 1600000
#define F    16

typedef unsigned long long ull;

// ---------------- scratch (static __device__, no allocs) ----------------
__device__ int g_deg[NN];
__device__ int g_cur[NN];
__device__ int g_off[NN + 1];
__device__ int g_bsum[128];
__device__ __align__(16) int2  g_sd[EMAX];                 // sorted (src,dst)
__device__ __align__(16) float g_eas[(size_t)EMAX * 8];    // sorted edge_attr
__device__ __align__(16) float g_P1[NN * F];               // conv1 src-partial
__device__ __align__(16) float g_P2[NN * F];               // conv2 src-partial
__device__ __align__(16) float g_h1[NN * F];
__device__ __align__(16) float g_h2[NN * F];
__device__ int g_idx64;

// ---------------- weights in constant memory ----------------
__constant__ __align__(16) float c1w1[16 * F];
__constant__ __align__(16) float c1b1[F];
__constant__ __align__(16) float c1w2[F * F];
__constant__ __align__(16) float c1b2[F];
__constant__ __align__(16) float c2w1[40 * F];
__constant__ __align__(16) float c2b1[F];
__constant__ __align__(16) float c2w2[F * F];
__constant__ __align__(16) float c2b2[F];
__constant__ __align__(16) float clw1[F * F];
__constant__ __align__(16) float clb1[F];
__constant__ __align__(16) float clw2[F];
__constant__ float clb2[1];

// ---------------- f32x2 packed helpers ----------------
__device__ __forceinline__ ull pk2(float a, float b) {
    ull r; asm("mov.b64 %0, {%1, %2};" : "=l"(r) : "f"(a), "f"(b)); return r;
}
__device__ __forceinline__ ull bcast2(float a) {
    ull r; asm("mov.b64 %0, {%1, %1};" : "=l"(r) : "f"(a)); return r;
}
__device__ __forceinline__ void upk2(ull v, float& a, float& b) {
    asm("mov.b64 {%0, %1}, %2;" : "=f"(a), "=f"(b) : "l"(v));
}
__device__ __forceinline__ ull fma2(ull a, ull b, ull c) {
    ull d; asm("fma.rn.f32x2 %0, %1, %2, %3;" : "=l"(d) : "l"(a), "l"(b), "l"(c)); return d;
}

// ---------------- preprocessing ----------------
__global__ void detect_kernel(const void* ei, int N) {
    const long long* p64 = (const long long*)ei;
    bool ok = true;
#pragma unroll
    for (int k = 0; k < 4; k++) {
        long long v = p64[k];
        if (v < 0 || v >= N) ok = false;
    }
    g_idx64 = ok ? 1 : 0;
}

// zero deg + h1 + h2
__global__ void zero_kernel(int N) {
    int i = blockIdx.x * blockDim.x + threadIdx.x;
    if (i < N) g_deg[i] = 0;
    int n4 = N * 4;  // N*F/4 float4s per h array
    if (i < n4) {
        reinterpret_cast<float4*>(g_h1)[i] = make_float4(0.f, 0.f, 0.f, 0.f);
        reinterpret_cast<float4*>(g_h2)[i] = make_float4(0.f, 0.f, 0.f, 0.f);
    }
}

__global__ void hist_kernel(const void* __restrict__ ei, int E) {
    int e = blockIdx.x * blockDim.x + threadIdx.x;
    if (e >= E) return;
    int s = g_idx64 ? (int)((const long long*)ei)[e] : ((const int*)ei)[e];
    atomicAdd(&g_deg[s], 1);
}

__global__ void __launch_bounds__(1024) scan_blocks_kernel(int n) {
    __shared__ int wsum[32];
    int i = blockIdx.x * 1024 + threadIdx.x;
    int lane = threadIdx.x & 31;
    int wid  = threadIdx.x >> 5;
    int v = (i < n) ? g_deg[i] : 0;
    int s = v;
#pragma unroll
    for (int o = 1; o < 32; o <<= 1) {
        int t = __shfl_up_sync(~0u, s, o);
        if (lane >= o) s += t;
    }
    if (lane == 31) wsum[wid] = s;
    __syncthreads();
    if (wid == 0) {
        int ws = wsum[lane];
#pragma unroll
        for (int o = 1; o < 32; o <<= 1) {
            int t = __shfl_up_sync(~0u, ws, o);
            if (lane >= o) ws += t;
        }
        wsum[lane] = ws;
    }
    __syncthreads();
    int excl = s - v + (wid > 0 ? wsum[wid - 1] : 0);
    if (i < n) g_off[i] = excl;
    if (threadIdx.x == 1023) g_bsum[blockIdx.x] = wsum[31];
}

__global__ void __launch_bounds__(128) scan_tops_kernel(int nb) {
    __shared__ int wsum[4];
    int lane = threadIdx.x & 31;
    int wid  = threadIdx.x >> 5;
    int v = (threadIdx.x < nb) ? g_bsum[threadIdx.x] : 0;
    int s = v;
#pragma unroll
    for (int o = 1; o < 32; o <<= 1) {
        int t = __shfl_up_sync(~0u, s, o);
        if (lane >= o) s += t;
    }
    if (lane == 31) wsum[wid] = s;
    __syncthreads();
    int base = 0;
#pragma unroll
    for (int k = 0; k < 4; k++) if (k < wid) base += wsum[k];
    if (threadIdx.x < nb) g_bsum[threadIdx.x] = base + s - v;
}

__global__ void __launch_bounds__(1024) add_offsets_kernel(int n, int E) {
    int i = blockIdx.x * 1024 + threadIdx.x;
    if (i < n) {
        int o = g_off[i] + g_bsum[blockIdx.x];
        g_cur[i] = o;
    }
}

__global__ void scatter_kernel(const void* __restrict__ ei,
                               const float* __restrict__ ea, int E) {
    int e = blockIdx.x * blockDim.x + threadIdx.x;
    if (e >= E) return;
    int s, d;
    if (g_idx64) {
        const long long* p = (const long long*)ei;
        s = (int)p[e]; d = (int)p[(size_t)E + e];
    } else {
        const int* p = (const int*)ei;
        s = p[e]; d = p[(size_t)E + e];
    }
    int pos = atomicAdd(&g_cur[s], 1);
    g_sd[pos] = make_int2(s, d);
    float4 a0 = *(const float4*)(ea + (size_t)e * 8);
    float4 a1 = *(const float4*)(ea + (size_t)e * 8 + 4);
    *(float4*)(g_eas + (size_t)pos * 8)     = a0;
    *(float4*)(g_eas + (size_t)pos * 8 + 4) = a1;
}

// ---------------- P1: conv1 src-partial per node ----------------
__global__ void __launch_bounds__(256) p1_kernel(const float* __restrict__ x, int N) {
    int n = blockIdx.x * blockDim.x + threadIdx.x;
    if (n >= N) return;
    const ull* w1p = reinterpret_cast<const ull*>(c1w1);
    float4 xv = *(const float4*)(x + (size_t)n * 4);
    float in[4] = {xv.x, xv.y, xv.z, xv.w};
    ull H[8];
#pragma unroll
    for (int k = 0; k < 8; k++) H[k] = pk2(c1b1[2*k], c1b1[2*k+1]);
#pragma unroll
    for (int i = 0; i < 4; i++) {
        ull vv = bcast2(in[i]);
#pragma unroll
        for (int k = 0; k < 8; k++) H[k] = fma2(vv, w1p[i*8 + k], H[k]);
    }
    ull* out = (ull*)(g_P1 + (size_t)n * F);
#pragma unroll
    for (int k = 0; k < 8; k++) out[k] = H[k];
}

// ---------------- P2: conv2 src-partial per node (reads final h1) ----------------
__global__ void __launch_bounds__(256) p2_kernel(int N) {
    int n = blockIdx.x * blockDim.x + threadIdx.x;
    if (n >= N) return;
    const ull* w1p = reinterpret_cast<const ull*>(c2w1);
    ull H[8];
#pragma unroll
    for (int k = 0; k < 8; k++) H[k] = pk2(c2b1[2*k], c2b1[2*k+1]);
    const float4* ph = (const float4*)(g_h1 + (size_t)n * F);
#pragma unroll
    for (int q = 0; q < 4; q++) {
        float4 v = ph[q];
        float hv[4] = {v.x, v.y, v.z, v.w};
#pragma unroll
        for (int r = 0; r < 4; r++) {
            ull vv = bcast2(hv[r]);
            int i = q * 4 + r;
#pragma unroll
            for (int k = 0; k < 8; k++) H[k] = fma2(vv, w1p[i*8 + k], H[k]);
        }
    }
    ull* out = (ull*)(g_P2 + (size_t)n * F);
#pragma unroll
    for (int k = 0; k < 8; k++) out[k] = H[k];
}

// ---------------- warp-segmented max + tail atomics ----------------
__device__ __forceinline__ void seg_max_commit(int s, float* o, float* hout) {
    int lane = threadIdx.x & 31;
#pragma unroll
    for (int off = 1; off < 32; off <<= 1) {
        int so = __shfl_up_sync(~0u, s, off);
        bool merge = (lane >= off) && (so == s);
#pragma unroll
        for (int f = 0; f < F; f++) {
            float v = __shfl_up_sync(~0u, o[f], off);
            if (merge) o[f] = fmaxf(o[f], v);
        }
    }
    int snext = __shfl_down_sync(~0u, s, 1);
    bool tail = (lane == 31) || (snext != s);
    if (tail) {
        int* hp = (int*)(hout + (size_t)s * F);
#pragma unroll
        for (int f = 0; f < F; f++)
            atomicMax(hp + f, __float_as_int(o[f]));   // baseline 0 => relu+clamp exact
    }
}

// ---------------- conv edge kernels: one lane = one sorted edge ----------------
__global__ void __launch_bounds__(256) conv1_edge_kernel(const float* __restrict__ x, int E) {
    int p = blockIdx.x * blockDim.x + threadIdx.x;
    p = min(p, E - 1);   // duplicates are harmless for max

    const ull* w1p = reinterpret_cast<const ull*>(c1w1);
    const ull* w2p = reinterpret_cast<const ull*>(c1w2);

    int2 sd = g_sd[p];
    ull H[8];
    {
        const ull* Pp = (const ull*)(g_P1 + (size_t)sd.x * F);
#pragma unroll
        for (int k = 0; k < 8; k++) H[k] = Pp[k];
    }
    float4 xj = *(const float4*)(x + (size_t)sd.y * 4);
    float4 a0 = *(const float4*)(g_eas + (size_t)p * 8);
    float4 a1 = *(const float4*)(g_eas + (size_t)p * 8 + 4);
    float in[12] = {xj.x, xj.y, xj.z, xj.w,
                    a0.x, a0.y, a0.z, a0.w, a1.x, a1.y, a1.z, a1.w};
#pragma unroll
    for (int i = 0; i < 12; i++) {
        ull vv = bcast2(in[i]);
#pragma unroll
        for (int k = 0; k < 8; k++) H[k] = fma2(vv, w1p[(4+i)*8 + k], H[k]);
    }

    ull O[8];
#pragma unroll
    for (int k = 0; k < 8; k++) O[k] = pk2(c1b2[2*k], c1b2[2*k+1]);
#pragma unroll
    for (int k = 0; k < 8; k++) {
        float a, b; upk2(H[k], a, b);
        a = fmaxf(a, 0.f); b = fmaxf(b, 0.f);
        ull va = bcast2(a), vb = bcast2(b);
#pragma unroll
        for (int m = 0; m < 8; m++) O[m] = fma2(va, w2p[(2*k)*8 + m], O[m]);
#pragma unroll
        for (int m = 0; m < 8; m++) O[m] = fma2(vb, w2p[(2*k+1)*8 + m], O[m]);
    }
    float o[F];
#pragma unroll
    for (int m = 0; m < 8; m++) upk2(O[m], o[2*m], o[2*m+1]);

    seg_max_commit(sd.x, o, g_h1);
}

__global__ void __launch_bounds__(256) conv2_edge_kernel(int E) {
    int p = blockIdx.x * blockDim.x + threadIdx.x;
    p = min(p, E - 1);

    const ull* w1p = reinterpret_cast<const ull*>(c2w1);
    const ull* w2p = reinterpret_cast<const ull*>(c2w2);

    int2 sd = g_sd[p];
    ull H[8];
    {
        const ull* Pp = (const ull*)(g_P2 + (size_t)sd.x * F);
#pragma unroll
        for (int k = 0; k < 8; k++) H[k] = Pp[k];
    }
    float in[24];
    {
        const float4* pd = (const float4*)(g_h1 + (size_t)sd.y * F);
#pragma unroll
        for (int q = 0; q < 4; q++) {
            float4 v = pd[q];
            in[q*4+0] = v.x; in[q*4+1] = v.y; in[q*4+2] = v.z; in[q*4+3] = v.w;
        }
        float4 a0 = *(const float4*)(g_eas + (size_t)p * 8);
        float4 a1 = *(const float4*)(g_eas + (size_t)p * 8 + 4);
        in[16] = a0.x; in[17] = a0.y; in[18] = a0.z; in[19] = a0.w;
        in[20] = a1.x; in[21] = a1.y; in[22] = a1.z; in[23] = a1.w;
    }
#pragma unroll
    for (int i = 0; i < 24; i++) {
        ull vv = bcast2(in[i]);
#pragma unroll
        for (int k = 0; k < 8; k++) H[k] = fma2(vv, w1p[(16+i)*8 + k], H[k]);
    }

    ull O[8];
#pragma unroll
    for (int k = 0; k < 8; k++) O[k] = pk2(c2b2[2*k], c2b2[2*k+1]);
#pragma unroll
    for (int k = 0; k < 8; k++) {
        float a, b; upk2(H[k], a, b);
        a = fmaxf(a, 0.f); b = fmaxf(b, 0.f);
        ull va = bcast2(a), vb = bcast2(b);
#pragma unroll
        for (int m = 0; m < 8; m++) O[m] = fma2(va, w2p[(2*k)*8 + m], O[m]);
#pragma unroll
        for (int m = 0; m < 8; m++) O[m] = fma2(vb, w2p[(2*k+1)*8 + m], O[m]);
    }
    float o[F];
#pragma unroll
    for (int m = 0; m < 8; m++) upk2(O[m], o[2*m], o[2*m+1]);

    seg_max_commit(sd.x, o, g_h2);
}

// ---------------- final node MLP (packed) ----------------
__global__ void __launch_bounds__(256) node_mlp_kernel(float* __restrict__ out, int n) {
    int i = blockIdx.x * blockDim.x + threadIdx.x;
    if (i >= n) return;

    const ull* w1p = reinterpret_cast<const ull*>(clw1);

    ull H[8];
#pragma unroll
    for (int k = 0; k < 8; k++) H[k] = pk2(clb1[2*k], clb1[2*k+1]);

    const float4* ph = (const float4*)(g_h2 + (size_t)i * F);
#pragma unroll
    for (int q = 0; q < 4; q++) {
        float4 v = ph[q];
        float hv[4] = {v.x, v.y, v.z, v.w};
#pragma unroll
        for (int r = 0; r < 4; r++) {
            ull vv = bcast2(hv[r]);
            int kk = q * 4 + r;
#pragma unroll
            for (int k = 0; k < 8; k++) H[k] = fma2(vv, w1p[kk*8 + k], H[k]);
        }
    }

    float acc = clb2[0];
#pragma unroll
    for (int k = 0; k < 8; k++) {
        float a, b; upk2(H[k], a, b);
        acc += fmaxf(a, 0.f) * clw2[2*k] + fmaxf(b, 0.f) * clw2[2*k+1];
    }
    out[i] = acc;
}

// ---------------- launch ----------------
extern "C" void kernel_launch(void* const* d_in, const int* in_sizes, int n_in,
                              void* d_out, int out_size)
{
    const float* x  = (const float*)d_in[0];
    const void*  ei = d_in[1];
    const float* ea = (const float*)d_in[2];

    int N = in_sizes[0] / 4;   // x is [N,4]
    int E = in_sizes[2] / 8;   // edge_attr is [E,8]
    float* out = (float*)d_out;

    cudaMemcpyToSymbolAsync(c1w1, d_in[3],  16 * F * sizeof(float), 0, cudaMemcpyDeviceToDevice);
    cudaMemcpyToSymbolAsync(c1b1, d_in[4],  F * sizeof(float),      0, cudaMemcpyDeviceToDevice);
    cudaMemcpyToSymbolAsync(c1w2, d_in[5],  F * F * sizeof(float),  0, cudaMemcpyDeviceToDevice);
    cudaMemcpyToSymbolAsync(c1b2, d_in[6],  F * sizeof(float),      0, cudaMemcpyDeviceToDevice);
    cudaMemcpyToSymbolAsync(c2w1, d_in[7],  40 * F * sizeof(float), 0, cudaMemcpyDeviceToDevice);
    cudaMemcpyToSymbolAsync(c2b1, d_in[8],  F * sizeof(float),      0, cudaMemcpyDeviceToDevice);
    cudaMemcpyToSymbolAsync(c2w2, d_in[9],  F * F * sizeof(float),  0, cudaMemcpyDeviceToDevice);
    cudaMemcpyToSymbolAsync(c2b2, d_in[10], F * sizeof(float),      0, cudaMemcpyDeviceToDevice);
    cudaMemcpyToSymbolAsync(clw1, d_in[11], F * F * sizeof(float),  0, cudaMemcpyDeviceToDevice);
    cudaMemcpyToSymbolAsync(clb1, d_in[12], F * sizeof(float),      0, cudaMemcpyDeviceToDevice);
    cudaMemcpyToSymbolAsync(clw2, d_in[13], F * sizeof(float),      0, cudaMemcpyDeviceToDevice);
    cudaMemcpyToSymbolAsync(clb2, d_in[14], 1 * sizeof(float),      0, cudaMemcpyDeviceToDevice);

    detect_kernel<<<1, 1>>>(ei, N);
    zero_kernel<<<(N * 4 + 255) / 256, 256>>>(N);

    int eblocks = (E + 255) / 256;
    hist_kernel<<<eblocks, 256>>>(ei, E);

    int sblocks = (N + 1023) / 1024;
    scan_blocks_kernel<<<sblocks, 1024>>>(N);
    scan_tops_kernel<<<1, 128>>>(sblocks);
    add_offsets_kernel<<<sblocks, 1024>>>(N, E);

    scatter_kernel<<<eblocks, 256>>>(ei, ea, E);
    p1_kernel<<<(N + 255) / 256, 256>>>(x, N);

    conv1_edge_kernel<<<eblocks, 256>>>(x, E);
    p2_kernel<<<(N + 255) / 256, 256>>>(N);
    conv2_edge_kernel<<<eblocks, 256>>>(E);

    node_mlp_kernel<<<(N + 255) / 256, 256>>>(out, N);
}